// round 11
// baseline (speedup 1.0000x reference)
#include <cuda_runtime.h>
#include <cstdint>

#define NMAX   100000
#define EHMAX  1600000
#define HD     32          // hidden dim (Hemb == Hgcn == 32)
#define NIN    128
#define SCB    512                        // nodes per scan block
#define NSBMAX ((NMAX + SCB - 1) / SCB)   // scan blocks (196)

// ---------------- device scratch (no allocations allowed) ----------------
__device__ __align__(16) float g_h  [NMAX * HD];   // relu(x@We + be)
__device__ __align__(16) float g_hw [NMAX * HD];   // dis * (h@Wg)  (pre-scaled)
__device__ float g_dis [NMAX];
__device__ int   g_cnt [NMAX];        // degree counts   (self-cleaned by k_gather)
__device__ int   g_rel [NMAX];        // fill cursors    (self-cleaned by k_gather)
__device__ int   g_loc [NMAX];        // per-block exclusive prefix
__device__ int   g_bsum[NSBMAX];      // block sums
__device__ int   g_bpre[NSBMAX];      // scanned block sums (exclusive)
__device__ int   g_tick;              // last-block ticket (self-resetting)
__device__ int   g_adj [2 * EHMAX];   // CSR adjacency

__device__ __forceinline__ int ldcg_i(const int* p) {
    int v;
    asm volatile("ld.global.cg.s32 %0, [%1];" : "=r"(v) : "l"(p));
    return v;
}

// ---------------- K0: fused embed + degree count -------------------------
__global__ __launch_bounds__(256) void k_embed(
    const float* __restrict__ x, const float* __restrict__ We,
    const float* __restrict__ be, const float* __restrict__ Wg,
    const int* __restrict__ row, const int* __restrict__ col,
    int n, int eh)
{
    // prologue: degree counting over the undirected edge list
    {
        int gtid = blockIdx.x * 256 + threadIdx.x;
        int gstride = gridDim.x * 256;
        for (int e = gtid; e < eh; e += gstride) {
            atomicAdd(&g_cnt[row[e]], 1);
            atomicAdd(&g_cnt[col[e]], 1);
        }
    }

    __shared__ float sWe[NIN * HD];
    __shared__ float sWg[HD * HD];
    __shared__ float sbe[HD];
    __shared__ float sx[8][2][NIN];

    int tid = threadIdx.x;
    for (int i = tid; i < NIN * HD; i += 256) sWe[i] = We[i];
    for (int i = tid; i < HD * HD;  i += 256) sWg[i] = Wg[i];
    if (tid < HD) sbe[tid] = be[tid];
    __syncthreads();

    int warp = tid >> 5, j = tid & 31;
    int n0 = (blockIdx.x * 8 + warp) * 2;
    int n1 = n0 + 1;
    bool v0 = n0 < n, v1 = n1 < n;

    if (v0) {
        const float* xr = x + (size_t)n0 * NIN;
        sx[warp][0][j] = xr[j]; sx[warp][0][j+32] = xr[j+32];
        sx[warp][0][j+64] = xr[j+64]; sx[warp][0][j+96] = xr[j+96];
    }
    if (v1) {
        const float* xr = x + (size_t)n1 * NIN;
        sx[warp][1][j] = xr[j]; sx[warp][1][j+32] = xr[j+32];
        sx[warp][1][j+64] = xr[j+64]; sx[warp][1][j+96] = xr[j+96];
    } else {
        sx[warp][1][j] = 0.f; sx[warp][1][j+32] = 0.f;
        sx[warp][1][j+64] = 0.f; sx[warp][1][j+96] = 0.f;
    }
    __syncwarp();
    if (!v0) return;

    float a0 = sbe[j], a1 = sbe[j];
    #pragma unroll
    for (int k = 0; k < NIN; k++) {
        float w = sWe[k * HD + j];
        a0 = fmaf(sx[warp][0][k], w, a0);
        a1 = fmaf(sx[warp][1][k], w, a1);
    }
    float h0 = fmaxf(a0, 0.f), h1 = fmaxf(a1, 0.f);
    g_h[n0 * HD + j] = h0;
    if (v1) g_h[n1 * HD + j] = h1;

    float c0 = 0.f, c1 = 0.f;
    #pragma unroll
    for (int k = 0; k < HD; k++) {
        float w = sWg[k * HD + j];
        c0 = fmaf(__shfl_sync(0xffffffffu, h0, k), w, c0);
        c1 = fmaf(__shfl_sync(0xffffffffu, h1, k), w, c1);
    }
    g_hw[n0 * HD + j] = c0;
    if (v1) g_hw[n1 * HD + j] = c1;
}

// ---------------- K1: fused scan (local + last-block global) + disscale --
__global__ __launch_bounds__(SCB) void k_scan(int n, int nsb) {
    __shared__ int s[SCB];
    __shared__ int isLast;
    int t = threadIdx.x;
    int i = blockIdx.x * SCB + t;
    int v = (i < n) ? g_cnt[i] : 0;
    s[t] = v;
    __syncthreads();
    #pragma unroll
    for (int off = 1; off < SCB; off <<= 1) {
        int xv = (t >= off) ? s[t - off] : 0;
        __syncthreads();
        s[t] += xv;
        __syncthreads();
    }
    if (i < n) g_loc[i] = s[t] - v;          // exclusive
    if (t == SCB - 1) g_bsum[blockIdx.x] = s[t];

    // disscale for this block's nodes: dis = rsqrt(cnt+1); hw *= dis
    {
        float4* hw4 = (float4*)g_hw;
        int base4 = blockIdx.x * SCB * 8;    // float4 index base
        #pragma unroll
        for (int q = 0; q < 8; q++) {
            int idx = base4 + q * SCB + t;
            if (idx < n * 8) {
                int node = idx >> 3;
                float dis = rsqrtf((float)g_cnt[node] + 1.0f);
                if ((idx & 7) == 0) g_dis[node] = dis;
                float4 w = hw4[idx];
                w.x *= dis; w.y *= dis; w.z *= dis; w.w *= dis;
                hw4[idx] = w;
            }
        }
    }

    __threadfence();
    if (t == 0) isLast = (atomicAdd(&g_tick, 1) == gridDim.x - 1);
    __syncthreads();
    if (!isLast) return;

    // final block: scan the block sums (nsb <= SCB)
    int bv = (t < nsb) ? ldcg_i(&g_bsum[t]) : 0;
    s[t] = bv;
    __syncthreads();
    #pragma unroll
    for (int off = 1; off < SCB; off <<= 1) {
        int xv = (t >= off) ? s[t - off] : 0;
        __syncthreads();
        s[t] += xv;
        __syncthreads();
    }
    if (t < nsb) g_bpre[t] = s[t] - bv;      // exclusive
    if (t == 0) g_tick = 0;                  // self-reset for next call
}

// ---------------- K2: CSR fill — 2 edges/thread, 4 atomic chains --------
__global__ void k_fill(const int* __restrict__ row, const int* __restrict__ col, int eh) {
    int i = blockIdx.x * blockDim.x + threadIdx.x;
    int e0 = i * 2;
    if (e0 >= eh) return;
    int s0, d0, s1 = -1, d1 = -1;
    if (e0 + 1 < eh) {
        int2 rr = ((const int2*)row)[i];
        int2 cc = ((const int2*)col)[i];
        s0 = rr.x; s1 = rr.y; d0 = cc.x; d1 = cc.y;
    } else {
        s0 = row[e0]; d0 = col[e0];
    }
    int bs0 = g_loc[s0] + g_bpre[s0 >> 9];
    int bd0 = g_loc[d0] + g_bpre[d0 >> 9];
    int ps0 = bs0 + atomicAdd(&g_rel[s0], 1);
    int pd0 = bd0 + atomicAdd(&g_rel[d0], 1);
    if (s1 >= 0) {
        int bs1 = g_loc[s1] + g_bpre[s1 >> 9];
        int bd1 = g_loc[d1] + g_bpre[d1 >> 9];
        int ps1 = bs1 + atomicAdd(&g_rel[s1], 1);
        int pd1 = bd1 + atomicAdd(&g_rel[d1], 1);
        g_adj[ps1] = d1;
        g_adj[pd1] = s1;
    }
    g_adj[ps0] = d0;
    g_adj[pd0] = s0;
}

// ---------------- K3: fused gather (att softmax + z + GCN agg) + final --
// Warp per node. sub = lane&7 (float4 slot), g = lane>>3 (neighbor group).
// 3-deep software pipeline: 12 neighbors in flight per warp.
__global__ __launch_bounds__(256) void k_gather(
    const float* __restrict__ t,
    const float* __restrict__ W1, const float* __restrict__ b1,
    const float* __restrict__ W2, const float* __restrict__ b2,
    const float* __restrict__ b_gcn,
    float* __restrict__ outp, float* __restrict__ repp, float* __restrict__ zoutp,
    int n)
{
    __shared__ float sW1[34 * HD];
    __shared__ float sb1[HD], sW2[HD], sb2s[1];
    __shared__ float sAcc[8][128];            // per-warp float4 transpose buffer

    int tid = threadIdx.x;
    for (int i = tid; i < 34 * HD; i += 256) sW1[i] = W1[i];
    if (tid < HD) { sb1[tid] = b1[tid]; sW2[tid] = W2[tid]; }
    if (tid == 0) sb2s[0] = b2[0];
    __syncthreads();

    int warp = tid >> 5, lane = tid & 31;
    int node = blockIdx.x * 8 + warp;
    if (node >= n) return;

    int sub = lane & 7;
    int g   = lane >> 3;
    unsigned gmask = 0xFFu << (g * 8);

    const float4* h4  = (const float4*)g_h;
    const float4* hw4 = (const float4*)g_hw;

    float4 hi = h4[(size_t)node * 8 + sub];
    int off = g_loc[node] + g_bpre[node >> 9];
    int cnt = g_cnt[node];

    // self-clean CSR state for the next kernel_launch call
    if (lane == 0) { g_cnt[node] = 0; g_rel[node] = 0; }

    float4 acc = make_float4(0.f, 0.f, 0.f, 0.f);
    float deno = 0.f, z = 0.f;

    int k = g;
    for (; k + 8 < cnt; k += 12) {
        int v0 = g_adj[off + k];
        int v1 = g_adj[off + k + 4];
        int v2 = g_adj[off + k + 8];
        float4 hv0  = h4 [(size_t)v0 * 8 + sub];
        float4 hv1  = h4 [(size_t)v1 * 8 + sub];
        float4 hv2  = h4 [(size_t)v2 * 8 + sub];
        float4 hwv0 = hw4[(size_t)v0 * 8 + sub];
        float4 hwv1 = hw4[(size_t)v1 * 8 + sub];
        float4 hwv2 = hw4[(size_t)v2 * 8 + sub];
        float  t0 = t[v0], t1 = t[v1], t2 = t[v2];

        float p0 = hi.x*hv0.x + hi.y*hv0.y + hi.z*hv0.z + hi.w*hv0.w;
        float p1 = hi.x*hv1.x + hi.y*hv1.y + hi.z*hv1.z + hi.w*hv1.w;
        float p2 = hi.x*hv2.x + hi.y*hv2.y + hi.z*hv2.z + hi.w*hv2.w;
        p0 += __shfl_xor_sync(gmask, p0, 1);
        p1 += __shfl_xor_sync(gmask, p1, 1);
        p2 += __shfl_xor_sync(gmask, p2, 1);
        p0 += __shfl_xor_sync(gmask, p0, 2);
        p1 += __shfl_xor_sync(gmask, p1, 2);
        p2 += __shfl_xor_sync(gmask, p2, 2);
        p0 += __shfl_xor_sync(gmask, p0, 4);
        p1 += __shfl_xor_sync(gmask, p1, 4);
        p2 += __shfl_xor_sync(gmask, p2, 4);
        float a0 = __expf(p0), a1 = __expf(p1), a2 = __expf(p2);
        deno += a0 + a1 + a2;
        z = fmaf(a0, t0, z); z = fmaf(a1, t1, z); z = fmaf(a2, t2, z);
        acc.x += hwv0.x + hwv1.x + hwv2.x;
        acc.y += hwv0.y + hwv1.y + hwv2.y;
        acc.z += hwv0.z + hwv1.z + hwv2.z;
        acc.w += hwv0.w + hwv1.w + hwv2.w;
    }
    for (; k < cnt; k += 4) {   // at most 2 remainder iterations per group
        int v = g_adj[off + k];
        float4 hv  = h4 [(size_t)v * 8 + sub];
        float4 hwv = hw4[(size_t)v * 8 + sub];
        float p = hi.x*hv.x + hi.y*hv.y + hi.z*hv.z + hi.w*hv.w;
        p += __shfl_xor_sync(gmask, p, 1);
        p += __shfl_xor_sync(gmask, p, 2);
        p += __shfl_xor_sync(gmask, p, 4);
        float a = __expf(p);
        deno += a;
        z = fmaf(a, t[v], z);
        acc.x += hwv.x; acc.y += hwv.y; acc.z += hwv.z; acc.w += hwv.w;
    }

    // deno/z: 8 lanes of each group hold identical partials -> warp tree
    // sum = 8 * (sum over groups); *0.125f is exact (power of two).
    #pragma unroll
    for (int o = 1; o < 32; o <<= 1) {
        deno += __shfl_xor_sync(0xffffffffu, deno, o);
        z    += __shfl_xor_sync(0xffffffffu, z,    o);
    }
    deno *= 0.125f; z *= 0.125f;

    // transpose acc (float4-per-lane) -> scalar-per-feature via smem
    sAcc[warp][lane * 4 + 0] = acc.x;
    sAcc[warp][lane * 4 + 1] = acc.y;
    sAcc[warp][lane * 4 + 2] = acc.z;
    sAcc[warp][lane * 4 + 3] = acc.w;
    __syncwarp();
    int slot = lane >> 2, comp = lane & 3;
    float aggj = 0.f;
    #pragma unroll
    for (int gg = 0; gg < 4; gg++)
        aggj += sAcc[warp][(gg * 8 + slot) * 4 + comp];

    // ---- final head, inline ----
    float dis = g_dis[node];
    float hwj = g_hw[(size_t)node * HD + lane];   // = dis*hw
    float hj  = g_h [(size_t)node * HD + lane];
    float gcn = dis * aggj + dis * hwj + b_gcn[lane];
    float rep = hj + fmaxf(gcn, 0.f);
    if (repp) repp[(size_t)node * HD + lane] = rep;

    float zi = z / (deno + 1e-8f);
    float ti = t[node];

    float accm = sb1[lane];
    #pragma unroll
    for (int kk = 0; kk < HD; kk++)
        accm = fmaf(__shfl_sync(0xffffffffu, rep, kk), sW1[kk * HD + lane], accm);
    accm = fmaf(ti, sW1[32 * HD + lane], accm);
    accm = fmaf(zi, sW1[33 * HD + lane], accm);
    accm = fmaxf(accm, 0.f);

    float o = accm * sW2[lane];
    #pragma unroll
    for (int offr = 16; offr > 0; offr >>= 1)
        o += __shfl_xor_sync(0xffffffffu, o, offr);
    if (lane == 0) outp[node] = o + sb2s[0];
    if (zoutp && lane == 1) zoutp[node] = zi;
}

// ---------------- host ----------------
extern "C" void kernel_launch(void* const* d_in, const int* in_sizes, int n_in,
                              void* d_out, int out_size)
{
    const float* x     = (const float*)d_in[0];
    const float* t     = (const float*)d_in[1];
    const int*   row   = (const int*)  d_in[2];
    const int*   col   = (const int*)  d_in[3];
    const float* W_emb = (const float*)d_in[4];
    const float* b_emb = (const float*)d_in[5];
    const float* W_gcn = (const float*)d_in[6];
    const float* b_gcn = (const float*)d_in[7];
    const float* W1    = (const float*)d_in[8];
    const float* b1    = (const float*)d_in[9];
    const float* W2    = (const float*)d_in[10];
    const float* b2    = (const float*)d_in[11];

    int n  = in_sizes[1];          // t has N elements
    int e2 = in_sizes[2];          // full directed edge count
    int eh = e2 / 2;               // symmetric half
    int nsb = (n + SCB - 1) / SCB;

    float* outp = (float*)d_out;
    bool full = (out_size == 34 * n);
    float* repp  = full ? outp + n      : nullptr;
    float* zoutp = full ? outp + 33 * n : nullptr;

    k_embed <<<(n + 15) / 16, 256>>>(x, W_emb, b_emb, W_gcn, row, col, n, eh); // idx 0
    k_scan  <<<nsb, SCB>>>(n, nsb);                                            // idx 1
    k_fill  <<<(eh + 511) / 512, 256>>>(row, col, eh);                         // idx 2
    k_gather<<<(n + 7) / 8, 256>>>(t, W1, b1, W2, b2, b_gcn, outp, repp, zoutp, n); // idx 3 (ncu)
}

// round 12
// speedup vs baseline: 1.0364x; 1.0364x over previous
#include <cuda_runtime.h>
#include <cstdint>

#define NMAX   100000
#define EHMAX  1600000
#define HD     32          // hidden dim (Hemb == Hgcn == 32)
#define NIN    128
#define SCB    512                        // nodes per scan block
#define NSBMAX ((NMAX + SCB - 1) / SCB)   // scan blocks (196)

// ---------------- device scratch (no allocations allowed) ----------------
__device__ __align__(16) float g_h  [NMAX * HD];   // relu(x@We + be)
__device__ __align__(16) float g_hw [NMAX * HD];   // dis * (h@Wg)  (pre-scaled)
__device__ float g_dis [NMAX];
__device__ int   g_cnt [NMAX];        // degree counts   (self-cleaned by k_gather)
__device__ int   g_rel [NMAX];        // fill cursors    (self-cleaned by k_gather)
__device__ int   g_loc [NMAX];        // per-block exclusive prefix
__device__ int   g_bsum[NSBMAX];      // block sums
__device__ int   g_bpre[NSBMAX];      // scanned block sums (exclusive)
__device__ int   g_tick;              // last-block ticket (self-resetting)
__device__ int   g_adj [2 * EHMAX];   // CSR adjacency

__device__ __forceinline__ int ldcg_i(const int* p) {
    int v;
    asm volatile("ld.global.cg.s32 %0, [%1];" : "=r"(v) : "l"(p));
    return v;
}

// ---------------- K0: fused embed + degree count -------------------------
__global__ __launch_bounds__(256) void k_embed(
    const float* __restrict__ x, const float* __restrict__ We,
    const float* __restrict__ be, const float* __restrict__ Wg,
    const int* __restrict__ row, const int* __restrict__ col,
    int n, int eh)
{
    // prologue: degree counting over the undirected edge list
    {
        int gtid = blockIdx.x * 256 + threadIdx.x;
        int gstride = gridDim.x * 256;
        for (int e = gtid; e < eh; e += gstride) {
            atomicAdd(&g_cnt[row[e]], 1);
            atomicAdd(&g_cnt[col[e]], 1);
        }
    }

    __shared__ float sWe[NIN * HD];
    __shared__ float sWg[HD * HD];
    __shared__ float sbe[HD];
    __shared__ float sx[8][2][NIN];

    int tid = threadIdx.x;
    for (int i = tid; i < NIN * HD; i += 256) sWe[i] = We[i];
    for (int i = tid; i < HD * HD;  i += 256) sWg[i] = Wg[i];
    if (tid < HD) sbe[tid] = be[tid];
    __syncthreads();

    int warp = tid >> 5, j = tid & 31;
    int n0 = (blockIdx.x * 8 + warp) * 2;
    int n1 = n0 + 1;
    bool v0 = n0 < n, v1 = n1 < n;

    if (v0) {
        const float* xr = x + (size_t)n0 * NIN;
        sx[warp][0][j] = xr[j]; sx[warp][0][j+32] = xr[j+32];
        sx[warp][0][j+64] = xr[j+64]; sx[warp][0][j+96] = xr[j+96];
    }
    if (v1) {
        const float* xr = x + (size_t)n1 * NIN;
        sx[warp][1][j] = xr[j]; sx[warp][1][j+32] = xr[j+32];
        sx[warp][1][j+64] = xr[j+64]; sx[warp][1][j+96] = xr[j+96];
    } else {
        sx[warp][1][j] = 0.f; sx[warp][1][j+32] = 0.f;
        sx[warp][1][j+64] = 0.f; sx[warp][1][j+96] = 0.f;
    }
    __syncwarp();
    if (!v0) return;

    float a0 = sbe[j], a1 = sbe[j];
    #pragma unroll
    for (int k = 0; k < NIN; k++) {
        float w = sWe[k * HD + j];
        a0 = fmaf(sx[warp][0][k], w, a0);
        a1 = fmaf(sx[warp][1][k], w, a1);
    }
    float h0 = fmaxf(a0, 0.f), h1 = fmaxf(a1, 0.f);
    g_h[n0 * HD + j] = h0;
    if (v1) g_h[n1 * HD + j] = h1;

    float c0 = 0.f, c1 = 0.f;
    #pragma unroll
    for (int k = 0; k < HD; k++) {
        float w = sWg[k * HD + j];
        c0 = fmaf(__shfl_sync(0xffffffffu, h0, k), w, c0);
        c1 = fmaf(__shfl_sync(0xffffffffu, h1, k), w, c1);
    }
    g_hw[n0 * HD + j] = c0;
    if (v1) g_hw[n1 * HD + j] = c1;
}

// ---------------- K1: fused scan (local + last-block global) + disscale --
__global__ __launch_bounds__(SCB) void k_scan(int n, int nsb) {
    __shared__ int s[SCB];
    __shared__ int isLast;
    int t = threadIdx.x;
    int i = blockIdx.x * SCB + t;
    int v = (i < n) ? g_cnt[i] : 0;
    s[t] = v;
    __syncthreads();
    #pragma unroll
    for (int off = 1; off < SCB; off <<= 1) {
        int xv = (t >= off) ? s[t - off] : 0;
        __syncthreads();
        s[t] += xv;
        __syncthreads();
    }
    if (i < n) g_loc[i] = s[t] - v;          // exclusive
    if (t == SCB - 1) g_bsum[blockIdx.x] = s[t];

    // disscale for this block's nodes: dis = rsqrt(cnt+1); hw *= dis
    {
        float4* hw4 = (float4*)g_hw;
        int base4 = blockIdx.x * SCB * 8;    // float4 index base
        #pragma unroll
        for (int q = 0; q < 8; q++) {
            int idx = base4 + q * SCB + t;
            if (idx < n * 8) {
                int node = idx >> 3;
                float dis = rsqrtf((float)g_cnt[node] + 1.0f);
                if ((idx & 7) == 0) g_dis[node] = dis;
                float4 w = hw4[idx];
                w.x *= dis; w.y *= dis; w.z *= dis; w.w *= dis;
                hw4[idx] = w;
            }
        }
    }

    __threadfence();
    if (t == 0) isLast = (atomicAdd(&g_tick, 1) == gridDim.x - 1);
    __syncthreads();
    if (!isLast) return;

    // final block: scan the block sums (nsb <= SCB)
    int bv = (t < nsb) ? ldcg_i(&g_bsum[t]) : 0;
    s[t] = bv;
    __syncthreads();
    #pragma unroll
    for (int off = 1; off < SCB; off <<= 1) {
        int xv = (t >= off) ? s[t - off] : 0;
        __syncthreads();
        s[t] += xv;
        __syncthreads();
    }
    if (t < nsb) g_bpre[t] = s[t] - bv;      // exclusive
    if (t == 0) g_tick = 0;                  // self-reset for next call
}

// ---------------- K2: CSR fill — 4 edges/thread, 8 atomic chains --------
__global__ void k_fill(const int* __restrict__ row, const int* __restrict__ col, int eh) {
    int i = blockIdx.x * blockDim.x + threadIdx.x;
    int e0 = i * 4;
    if (e0 >= eh) return;
    if (e0 + 3 < eh) {
        int4 rr = ((const int4*)row)[i];
        int4 cc = ((const int4*)col)[i];
        int ps0 = g_loc[rr.x] + g_bpre[rr.x >> 9] + atomicAdd(&g_rel[rr.x], 1);
        int pd0 = g_loc[cc.x] + g_bpre[cc.x >> 9] + atomicAdd(&g_rel[cc.x], 1);
        int ps1 = g_loc[rr.y] + g_bpre[rr.y >> 9] + atomicAdd(&g_rel[rr.y], 1);
        int pd1 = g_loc[cc.y] + g_bpre[cc.y >> 9] + atomicAdd(&g_rel[cc.y], 1);
        int ps2 = g_loc[rr.z] + g_bpre[rr.z >> 9] + atomicAdd(&g_rel[rr.z], 1);
        int pd2 = g_loc[cc.z] + g_bpre[cc.z >> 9] + atomicAdd(&g_rel[cc.z], 1);
        int ps3 = g_loc[rr.w] + g_bpre[rr.w >> 9] + atomicAdd(&g_rel[rr.w], 1);
        int pd3 = g_loc[cc.w] + g_bpre[cc.w >> 9] + atomicAdd(&g_rel[cc.w], 1);
        g_adj[ps0] = cc.x;  g_adj[pd0] = rr.x;
        g_adj[ps1] = cc.y;  g_adj[pd1] = rr.y;
        g_adj[ps2] = cc.z;  g_adj[pd2] = rr.z;
        g_adj[ps3] = cc.w;  g_adj[pd3] = rr.w;
    } else {
        for (int e = e0; e < eh; e++) {
            int s = row[e], d = col[e];
            int ps = g_loc[s] + g_bpre[s >> 9] + atomicAdd(&g_rel[s], 1);
            g_adj[ps] = d;
            int pd = g_loc[d] + g_bpre[d >> 9] + atomicAdd(&g_rel[d], 1);
            g_adj[pd] = s;
        }
    }
}

// ---------------- K3: fused gather (att softmax + z + GCN agg) + final --
// Warp per node. sub = lane&7 (float4 slot), g = lane>>3 (neighbor group).
// 2-deep pipeline (8 neighbors in flight/warp); minBlocks=5 caps regs so
// occupancy stays >= 40 warps/SM — R11 showed 3-deep (60 regs, occ 43%)
// loses more to occupancy than it gains in per-warp MLP.
__global__ __launch_bounds__(256, 5) void k_gather(
    const float* __restrict__ t,
    const float* __restrict__ W1, const float* __restrict__ b1,
    const float* __restrict__ W2, const float* __restrict__ b2,
    const float* __restrict__ b_gcn,
    float* __restrict__ outp, float* __restrict__ repp, float* __restrict__ zoutp,
    int n)
{
    __shared__ float sW1[34 * HD];
    __shared__ float sb1[HD], sW2[HD], sb2s[1];
    __shared__ float sAcc[8][128];            // per-warp float4 transpose buffer

    int tid = threadIdx.x;
    for (int i = tid; i < 34 * HD; i += 256) sW1[i] = W1[i];
    if (tid < HD) { sb1[tid] = b1[tid]; sW2[tid] = W2[tid]; }
    if (tid == 0) sb2s[0] = b2[0];
    __syncthreads();

    int warp = tid >> 5, lane = tid & 31;
    int node = blockIdx.x * 8 + warp;
    if (node >= n) return;

    int sub = lane & 7;
    int g   = lane >> 3;
    unsigned gmask = 0xFFu << (g * 8);

    const float4* h4  = (const float4*)g_h;
    const float4* hw4 = (const float4*)g_hw;

    float4 hi = h4[(size_t)node * 8 + sub];
    int off = g_loc[node] + g_bpre[node >> 9];
    int cnt = g_cnt[node];

    // self-clean CSR state for the next kernel_launch call
    if (lane == 0) { g_cnt[node] = 0; g_rel[node] = 0; }

    float4 acc = make_float4(0.f, 0.f, 0.f, 0.f);
    float deno = 0.f, z = 0.f;

    int k = g;
    for (; k + 4 < cnt; k += 8) {
        int v0 = g_adj[off + k];
        int v1 = g_adj[off + k + 4];
        float4 hv0  = h4 [(size_t)v0 * 8 + sub];
        float4 hv1  = h4 [(size_t)v1 * 8 + sub];
        float4 hwv0 = hw4[(size_t)v0 * 8 + sub];
        float4 hwv1 = hw4[(size_t)v1 * 8 + sub];
        float  t0   = t[v0];
        float  t1   = t[v1];

        float p0 = hi.x*hv0.x + hi.y*hv0.y + hi.z*hv0.z + hi.w*hv0.w;
        float p1 = hi.x*hv1.x + hi.y*hv1.y + hi.z*hv1.z + hi.w*hv1.w;
        p0 += __shfl_xor_sync(gmask, p0, 1);
        p1 += __shfl_xor_sync(gmask, p1, 1);
        p0 += __shfl_xor_sync(gmask, p0, 2);
        p1 += __shfl_xor_sync(gmask, p1, 2);
        p0 += __shfl_xor_sync(gmask, p0, 4);
        p1 += __shfl_xor_sync(gmask, p1, 4);
        float a0 = __expf(p0);
        float a1 = __expf(p1);
        deno += a0 + a1;
        z = fmaf(a0, t0, z);
        z = fmaf(a1, t1, z);
        acc.x += hwv0.x + hwv1.x;
        acc.y += hwv0.y + hwv1.y;
        acc.z += hwv0.z + hwv1.z;
        acc.w += hwv0.w + hwv1.w;
    }
    if (k < cnt) {  // at most one remainder per group
        int v = g_adj[off + k];
        float4 hv  = h4 [(size_t)v * 8 + sub];
        float4 hwv = hw4[(size_t)v * 8 + sub];
        float p = hi.x*hv.x + hi.y*hv.y + hi.z*hv.z + hi.w*hv.w;
        p += __shfl_xor_sync(gmask, p, 1);
        p += __shfl_xor_sync(gmask, p, 2);
        p += __shfl_xor_sync(gmask, p, 4);
        float a = __expf(p);
        deno += a;
        z = fmaf(a, t[v], z);
        acc.x += hwv.x; acc.y += hwv.y; acc.z += hwv.z; acc.w += hwv.w;
    }

    // deno/z: 8 lanes of each group hold identical partials -> warp tree
    // sum = 8 * (sum over groups); *0.125f is exact (power of two).
    #pragma unroll
    for (int o = 1; o < 32; o <<= 1) {
        deno += __shfl_xor_sync(0xffffffffu, deno, o);
        z    += __shfl_xor_sync(0xffffffffu, z,    o);
    }
    deno *= 0.125f; z *= 0.125f;

    // transpose acc (float4-per-lane) -> scalar-per-feature via smem
    sAcc[warp][lane * 4 + 0] = acc.x;
    sAcc[warp][lane * 4 + 1] = acc.y;
    sAcc[warp][lane * 4 + 2] = acc.z;
    sAcc[warp][lane * 4 + 3] = acc.w;
    __syncwarp();
    int slot = lane >> 2, comp = lane & 3;
    float aggj = 0.f;
    #pragma unroll
    for (int gg = 0; gg < 4; gg++)
        aggj += sAcc[warp][(gg * 8 + slot) * 4 + comp];

    // ---- final head, inline ----
    float dis = g_dis[node];
    float hwj = g_hw[(size_t)node * HD + lane];   // = dis*hw
    float hj  = g_h [(size_t)node * HD + lane];
    float gcn = dis * aggj + dis * hwj + b_gcn[lane];
    float rep = hj + fmaxf(gcn, 0.f);
    if (repp) repp[(size_t)node * HD + lane] = rep;

    float zi = z / (deno + 1e-8f);
    float ti = t[node];

    float accm = sb1[lane];
    #pragma unroll
    for (int kk = 0; kk < HD; kk++)
        accm = fmaf(__shfl_sync(0xffffffffu, rep, kk), sW1[kk * HD + lane], accm);
    accm = fmaf(ti, sW1[32 * HD + lane], accm);
    accm = fmaf(zi, sW1[33 * HD + lane], accm);
    accm = fmaxf(accm, 0.f);

    float o = accm * sW2[lane];
    #pragma unroll
    for (int offr = 16; offr > 0; offr >>= 1)
        o += __shfl_xor_sync(0xffffffffu, o, offr);
    if (lane == 0) outp[node] = o + sb2s[0];
    if (zoutp && lane == 1) zoutp[node] = zi;
}

// ---------------- host ----------------
extern "C" void kernel_launch(void* const* d_in, const int* in_sizes, int n_in,
                              void* d_out, int out_size)
{
    const float* x     = (const float*)d_in[0];
    const float* t     = (const float*)d_in[1];
    const int*   row   = (const int*)  d_in[2];
    const int*   col   = (const int*)  d_in[3];
    const float* W_emb = (const float*)d_in[4];
    const float* b_emb = (const float*)d_in[5];
    const float* W_gcn = (const float*)d_in[6];
    const float* b_gcn = (const float*)d_in[7];
    const float* W1    = (const float*)d_in[8];
    const float* b1    = (const float*)d_in[9];
    const float* W2    = (const float*)d_in[10];
    const float* b2    = (const float*)d_in[11];

    int n  = in_sizes[1];          // t has N elements
    int e2 = in_sizes[2];          // full directed edge count
    int eh = e2 / 2;               // symmetric half
    int nsb = (n + SCB - 1) / SCB;

    float* outp = (float*)d_out;
    bool full = (out_size == 34 * n);
    float* repp  = full ? outp + n      : nullptr;
    float* zoutp = full ? outp + 33 * n : nullptr;

    k_embed <<<(n + 15) / 16, 256>>>(x, W_emb, b_emb, W_gcn, row, col, n, eh); // idx 0
    k_scan  <<<nsb, SCB>>>(n, nsb);                                            // idx 1
    k_fill  <<<(eh + 1023) / 1024, 256>>>(row, col, eh);                       // idx 2
    k_gather<<<(n + 7) / 8, 256>>>(t, W1, b1, W2, b2, b_gcn, outp, repp, zoutp, n); // idx 3 (ncu)
}